// round 6
// baseline (speedup 1.0000x reference)
#include <cuda_runtime.h>
#include <cuda_bf16.h>
#include <math.h>
#include <float.h>

#define BQ 64
#define DIM 768
#define NKEYS 262144
#define VOCAB 50257
#define KNN 8
#define INV_TEMP 0.1f
#define LAM 0.25f
#define EPSV 1e-10f

typedef unsigned long long u64;

// scratch
__device__ float g_scores[(size_t)BQ * NKEYS];          // 64 MiB
__device__ float g_w[BQ * KNN];
__device__ int   g_tok[BQ * KNN];
#define TCH 16
__device__ float g_cand_v[BQ * TCH * KNN];
__device__ int   g_cand_i[BQ * TCH * KNN];
#define ECH 8
__device__ float2 g_ms[BQ * ECH];

// ---------------------------------------------------------------------------
// Kernel A: score GEMM with packed fp32 (fma.rn.f32x2).
// s[b,n] = (2q).k - ||k||^2.  BM=64, BN=256, BK=16, 256 thr, 8x8 micro-tile
// held as 8x4 packed f32x2 accumulators.
// ---------------------------------------------------------------------------
#define BN 256
#define BK 16

__device__ __forceinline__ u64 pack_dup(float a) {
    u64 r;
    asm("mov.b64 %0, {%1, %1};" : "=l"(r) : "f"(a));
    return r;
}
__device__ __forceinline__ void unpack2(u64 v, float& lo, float& hi) {
    asm("mov.b64 {%0, %1}, %2;" : "=f"(lo), "=f"(hi) : "l"(v));
}

__global__ __launch_bounds__(256, 2) void gemm_score_kernel(
    const float* __restrict__ Q, const float* __restrict__ Keys)
{
    __shared__ float As[BK][BQ];    // holds 2*q
    __shared__ float Bs[BK][BN];
    __shared__ float k2sm[BN];

    const int tid = threadIdx.x;
    const int n0  = blockIdx.x * BN;

    const int alr = tid >> 2;          // A row 0..63
    const int als = (tid & 3) * 4;     // A k-seg
    const float* qb = Q + alr * DIM + als;
    const float* kb = Keys + (size_t)(n0 + tid) * DIM;

    const int tn = tid >> 3;           // 0..31 (n block of 8)
    const int tm = tid & 7;            // 0..7  (m block of 8)

    u64 acc2[8][4];
    const u64 zz = 0ull;
#pragma unroll
    for (int i = 0; i < 8; i++)
#pragma unroll
        for (int j = 0; j < 4; j++) acc2[i][j] = zz;

    float k2part = 0.f;

    for (int kk = 0; kk < DIM; kk += BK) {
        float4 a4 = *(const float4*)(qb + kk);
        float4 b0 = *(const float4*)(kb + kk);
        float4 b1 = *(const float4*)(kb + kk + 4);
        float4 b2 = *(const float4*)(kb + kk + 8);
        float4 b3 = *(const float4*)(kb + kk + 12);

        As[als + 0][alr] = 2.f * a4.x; As[als + 1][alr] = 2.f * a4.y;
        As[als + 2][alr] = 2.f * a4.z; As[als + 3][alr] = 2.f * a4.w;

        Bs[0][tid] = b0.x;  Bs[1][tid] = b0.y;  Bs[2][tid] = b0.z;  Bs[3][tid] = b0.w;
        Bs[4][tid] = b1.x;  Bs[5][tid] = b1.y;  Bs[6][tid] = b1.z;  Bs[7][tid] = b1.w;
        Bs[8][tid] = b2.x;  Bs[9][tid] = b2.y;  Bs[10][tid] = b2.z; Bs[11][tid] = b2.w;
        Bs[12][tid] = b3.x; Bs[13][tid] = b3.y; Bs[14][tid] = b3.z; Bs[15][tid] = b3.w;

        k2part += b0.x*b0.x + b0.y*b0.y + b0.z*b0.z + b0.w*b0.w
                + b1.x*b1.x + b1.y*b1.y + b1.z*b1.z + b1.w*b1.w
                + b2.x*b2.x + b2.y*b2.y + b2.z*b2.z + b2.w*b2.w
                + b3.x*b3.x + b3.y*b3.y + b3.z*b3.z + b3.w*b3.w;
        __syncthreads();

#pragma unroll
        for (int k = 0; k < BK; k++) {
            float4 av0 = *(const float4*)(&As[k][tm * 8]);
            float4 av1 = *(const float4*)(&As[k][tm * 8 + 4]);
            ulonglong2 bq0 = *(const ulonglong2*)(&Bs[k][tn * 8]);
            ulonglong2 bq1 = *(const ulonglong2*)(&Bs[k][tn * 8 + 4]);
            u64 bb[4] = {bq0.x, bq0.y, bq1.x, bq1.y};
            u64 aa[8];
            aa[0] = pack_dup(av0.x); aa[1] = pack_dup(av0.y);
            aa[2] = pack_dup(av0.z); aa[3] = pack_dup(av0.w);
            aa[4] = pack_dup(av1.x); aa[5] = pack_dup(av1.y);
            aa[6] = pack_dup(av1.z); aa[7] = pack_dup(av1.w);
#pragma unroll
            for (int i = 0; i < 8; i++)
#pragma unroll
                for (int j = 0; j < 4; j++)
                    asm("fma.rn.f32x2 %0, %1, %2, %0;"
                        : "+l"(acc2[i][j]) : "l"(aa[i]), "l"(bb[j]));
        }
        __syncthreads();
    }

    k2sm[tid] = k2part;
    __syncthreads();

    float k2[8];
#pragma unroll
    for (int j = 0; j < 8; j++) k2[j] = k2sm[tn * 8 + j];

#pragma unroll
    for (int i = 0; i < 8; i++) {
        int m = tm * 8 + i;
        float* op = g_scores + (size_t)m * NKEYS + n0 + tn * 8;
        float v[8];
#pragma unroll
        for (int j = 0; j < 4; j++) unpack2(acc2[i][j], v[2*j], v[2*j+1]);
        float4 o0, o1;
        o0.x = v[0] - k2[0]; o0.y = v[1] - k2[1];
        o0.z = v[2] - k2[2]; o0.w = v[3] - k2[3];
        o1.x = v[4] - k2[4]; o1.y = v[5] - k2[5];
        o1.z = v[6] - k2[6]; o1.w = v[7] - k2[7];
        *(float4*)(op)     = o0;
        *(float4*)(op + 4) = o1;
    }
}

// ---------------------------------------------------------------------------
// Kernel B1: per-(row,chunk) top-8.  grid (TCH, BQ), 256 threads.
// ---------------------------------------------------------------------------
#define CHUNK_N (NKEYS / TCH)

__global__ __launch_bounds__(256) void topk_stage1(void)
{
    const int chunk = blockIdx.x;
    const int row   = blockIdx.y;
    const int tid   = threadIdx.x;

    float tv[KNN]; int ti[KNN];
#pragma unroll
    for (int j = 0; j < KNN; j++) { tv[j] = -FLT_MAX; ti[j] = -1; }

    const float4* sp = (const float4*)(g_scores + (size_t)row * NKEYS + (size_t)chunk * CHUNK_N);
    const int nvec = CHUNK_N / 4;
    for (int i = tid; i < nvec; i += 256) {
        float4 s4 = sp[i];
        float v[4] = {s4.x, s4.y, s4.z, s4.w};
#pragma unroll
        for (int l = 0; l < 4; l++) {
            if (v[l] > tv[0]) {
                tv[0] = v[l]; ti[0] = chunk * CHUNK_N + i * 4 + l;
#pragma unroll
                for (int j = 0; j < KNN - 1; j++) {
                    if (tv[j] > tv[j + 1]) {
                        float t0 = tv[j]; tv[j] = tv[j+1]; tv[j+1] = t0;
                        int   t1 = ti[j]; ti[j] = ti[j+1]; ti[j+1] = t1;
                    }
                }
            }
        }
    }

    __shared__ float sv[256 * KNN];
    __shared__ int   si[256 * KNN];
#pragma unroll
    for (int j = 0; j < KNN; j++) { sv[tid*KNN+j] = tv[j]; si[tid*KNN+j] = ti[j]; }

    __shared__ float rv[256];
    __shared__ int   rp[256];
    __syncthreads();

    for (int sel = 0; sel < KNN; sel++) {
        float bv = -FLT_MAX; int bp = 0;
#pragma unroll
        for (int j = 0; j < KNN; j++) {
            float v = sv[tid*KNN+j];
            if (v > bv) { bv = v; bp = tid*KNN+j; }
        }
        rv[tid] = bv; rp[tid] = bp;
        __syncthreads();
        for (int s = 128; s > 0; s >>= 1) {
            if (tid < s && rv[tid+s] > rv[tid]) { rv[tid] = rv[tid+s]; rp[tid] = rp[tid+s]; }
            __syncthreads();
        }
        if (tid == 0) {
            int p = rp[0];
            g_cand_v[(row * TCH + chunk) * KNN + sel] = sv[p];
            g_cand_i[(row * TCH + chunk) * KNN + sel] = si[p];
            sv[p] = -FLT_MAX;
        }
        __syncthreads();
    }
}

// ---------------------------------------------------------------------------
// Kernel B2: merge 128 candidates per row -> top-8, weights, tokens.
// ---------------------------------------------------------------------------
__global__ __launch_bounds__(128) void topk_stage2(const int* __restrict__ values)
{
    const int row = blockIdx.x;
    const int tid = threadIdx.x;

    __shared__ float sv[128];
    __shared__ int   si[128];
    __shared__ float rv[128];
    __shared__ int   rp[128];
    __shared__ float topv[KNN];
    __shared__ int   topi[KNN];

    sv[tid] = g_cand_v[row * 128 + tid];
    si[tid] = g_cand_i[row * 128 + tid];
    __syncthreads();

    for (int sel = 0; sel < KNN; sel++) {
        rv[tid] = sv[tid]; rp[tid] = tid;
        __syncthreads();
        for (int s = 64; s > 0; s >>= 1) {
            if (tid < s && rv[tid+s] > rv[tid]) { rv[tid] = rv[tid+s]; rp[tid] = rp[tid+s]; }
            __syncthreads();
        }
        if (tid == 0) {
            int p = rp[0];
            topv[sel] = sv[p];
            topi[sel] = si[p];
            sv[p] = -FLT_MAX;
        }
        __syncthreads();
    }

    if (tid == 0) {
        float m = topv[0];
        float e[KNN], sum = 0.f;
#pragma unroll
        for (int j = 0; j < KNN; j++) { e[j] = expf((topv[j] - m) * INV_TEMP); sum += e[j]; }
        float inv = 1.f / sum;
#pragma unroll
        for (int j = 0; j < KNN; j++) {
            g_w[row * KNN + j]   = e[j] * inv;
            g_tok[row * KNN + j] = values[topi[j]];
        }
    }
}

// ---------------------------------------------------------------------------
// Kernel E1: per-(row,chunk) softmax partials. grid (ECH, BQ).
// ---------------------------------------------------------------------------
#define VCH ((VOCAB + ECH - 1) / ECH)

__global__ __launch_bounds__(256) void epi_partials(const float* __restrict__ base)
{
    const int chunk = blockIdx.x;
    const int row   = blockIdx.y;
    const int tid   = threadIdx.x;
    const int start = chunk * VCH;
    const int end   = min(start + VCH, VOCAB);
    const float* br = base + (size_t)row * VOCAB;

    __shared__ float red[256];

    float m = -FLT_MAX;
    for (int i = start + tid; i < end; i += 256) m = fmaxf(m, br[i]);
    red[tid] = m; __syncthreads();
    for (int s = 128; s > 0; s >>= 1) {
        if (tid < s) red[tid] = fmaxf(red[tid], red[tid+s]);
        __syncthreads();
    }
    const float mx = red[0];
    __syncthreads();

    float sacc = 0.f;
    for (int i = start + tid; i < end; i += 256) sacc += expf(br[i] - mx);
    red[tid] = sacc; __syncthreads();
    for (int s = 128; s > 0; s >>= 1) {
        if (tid < s) red[tid] += red[tid+s];
        __syncthreads();
    }
    if (tid == 0) g_ms[row * ECH + chunk] = make_float2(mx, red[0]);
}

// ---------------------------------------------------------------------------
// Kernel E2: elementwise mix + 3 output streams. grid (ECH, BQ).
// ---------------------------------------------------------------------------
__global__ __launch_bounds__(256) void epi_write(
    const float* __restrict__ base, float* __restrict__ out)
{
    const int chunk = blockIdx.x;
    const int row   = blockIdx.y;
    const int tid   = threadIdx.x;
    const int start = chunk * VCH;
    const int end   = min(start + VCH, VOCAB);
    const float* br = base + (size_t)row * VOCAB;

    float mx = -FLT_MAX;
#pragma unroll
    for (int c = 0; c < ECH; c++) mx = fmaxf(mx, g_ms[row * ECH + c].x);
    float Z = 0.f;
#pragma unroll
    for (int c = 0; c < ECH; c++) {
        float2 p = g_ms[row * ECH + c];
        Z += p.y * expf(p.x - mx);
    }
    const float invZ = 1.f / Z;

    float w[KNN]; int tk[KNN];
#pragma unroll
    for (int j = 0; j < KNN; j++) { w[j] = g_w[row*KNN+j]; tk[j] = g_tok[row*KNN+j]; }

    const float invden = 1.f / (1.f + (float)VOCAB * EPSV);

    float* oi = out + (size_t)row * VOCAB;
    float* ob = out + (size_t)BQ * VOCAB + (size_t)row * VOCAB;
    float* ok = out + (size_t)2 * BQ * VOCAB + (size_t)row * VOCAB;

    for (int i = start + tid; i < end; i += 256) {
        float b  = br[i];
        float sb = expf(b - mx) * invZ;
        float tp = 0.f;
#pragma unroll
        for (int j = 0; j < KNN; j++) tp += (tk[j] == i) ? w[j] : 0.f;
        float p = (1.f - LAM) * sb + LAM * (tp + EPSV) * invden;
        oi[i] = logf(p);
        ob[i] = b;
        ok[i] = logf(tp + EPSV);
    }
}

// ---------------------------------------------------------------------------
extern "C" void kernel_launch(void* const* d_in, const int* in_sizes, int n_in,
                              void* d_out, int out_size)
{
    const float* Q    = (const float*)d_in[0];
    const float* BL   = (const float*)d_in[1];
    const float* Keys = (const float*)d_in[2];
    const int*   Vals = (const int*)d_in[3];
    float* out = (float*)d_out;

    gemm_score_kernel<<<NKEYS / BN, 256>>>(Q, Keys);
    topk_stage1<<<dim3(TCH, BQ), 256>>>();
    topk_stage2<<<BQ, 128>>>(Vals);
    epi_partials<<<dim3(ECH, BQ), 256>>>(BL);
    epi_write<<<dim3(ECH, BQ), 256>>>(BL, out);
}

// round 10
// speedup vs baseline: 2.5440x; 2.5440x over previous
#include <cuda_runtime.h>
#include <cuda_bf16.h>
#include <math.h>
#include <float.h>
#include <stdint.h>

#define BQ 64
#define DIM 768
#define NKEYS 262144
#define VOCAB 50257
#define KNN 8
#define INV_TEMP 0.1f
#define LAM 0.25f
#define EPSV 1e-10f

#define BM 128                 // keys per CTA
#define KF 32                  // fp32 elems per k-chunk
#define NCH (DIM / KF)         // 24
#define NKB (NKEYS / BM)       // 2048
#define ASTRIDE 40             // bf16 row stride (80 B) -> conflict-free ldmatrix

// blocked scores: g_scores[(kb*64 + q)*128 + m]
__device__ float g_scores[(size_t)BQ * NKEYS];
__device__ float g_w[BQ * KNN];
__device__ int   g_tok[BQ * KNN];
#define TCH 16
#define CAND16 16
__device__ float g_cand_v[BQ * TCH * KNN];
__device__ int   g_cand_i[BQ * TCH * KNN];
#define ECH 8
__device__ float2 g_ms[BQ * ECH];

// ---------------- warp-MMA helpers (sm_80 baseline ops, valid on compute_103) --
__device__ __forceinline__ void ldsm_x4(uint32_t* r, uint32_t addr) {
    asm volatile("ldmatrix.sync.aligned.m8n8.x4.shared.b16 {%0,%1,%2,%3}, [%4];"
                 : "=r"(r[0]), "=r"(r[1]), "=r"(r[2]), "=r"(r[3]) : "r"(addr));
}
__device__ __forceinline__ void mma_bf16(float* d, const uint32_t* a, const uint32_t* b) {
    asm volatile("mma.sync.aligned.m16n8k16.row.col.f32.bf16.bf16.f32 "
                 "{%0,%1,%2,%3}, {%4,%5,%6,%7}, {%8,%9}, {%0,%1,%2,%3};"
                 : "+f"(d[0]), "+f"(d[1]), "+f"(d[2]), "+f"(d[3])
                 : "r"(a[0]), "r"(a[1]), "r"(a[2]), "r"(a[3]), "r"(b[0]), "r"(b[1]));
}

// ---------------------------------------------------------------------------
// Kernel A: bf16 tensor-core score GEMM.
// D[m][q] = (2*Q[q]) . Keys[m] (bf16 mma, fp32 accum);  s = D - ||k||^2 (fp32)
// ---------------------------------------------------------------------------
__global__ __launch_bounds__(256) void gemm_mma_kernel(
    const float* __restrict__ Q, const float* __restrict__ Keys)
{
    __shared__ __nv_bfloat16 As2[2][BM][ASTRIDE];
    __shared__ __nv_bfloat16 Bs2[2][BQ][ASTRIDE];
    __shared__ float k2sm[BM];

    const int tid = threadIdx.x;
    const int wid = tid >> 5, lid = tid & 31;
    const int m0 = blockIdx.x * BM;
    const int warp_m = (wid >> 1) * 32;   // 4 warps along keys
    const int warp_n = (wid & 1) * 32;    // 2 warps along queries

    const int lrow = tid >> 3;            // 0..31
    const int lc4  = tid & 7;             // float4 slot within 32-float chunk

    float acc[2][4][4];
#pragma unroll
    for (int a = 0; a < 2; a++)
#pragma unroll
        for (int b = 0; b < 4; b++)
#pragma unroll
            for (int e = 0; e < 4; e++) acc[a][b][e] = 0.f;

    float k2acc[4] = {0.f, 0.f, 0.f, 0.f};
    float4 ka[4], qa[2];

    auto load_chunk = [&](int c) {
        const int kc = c * KF;
#pragma unroll
        for (int p = 0; p < 4; p++) {
            int row = lrow + 32 * p;
            ka[p] = *(const float4*)(Keys + (size_t)(m0 + row) * DIM + kc + lc4 * 4);
        }
#pragma unroll
        for (int p = 0; p < 2; p++) {
            int row = lrow + 32 * p;
            qa[p] = *(const float4*)(Q + (size_t)row * DIM + kc + lc4 * 4);
        }
    };
    auto store_chunk = [&](int s) {
#pragma unroll
        for (int p = 0; p < 4; p++) {
            int row = lrow + 32 * p;
            float4 v = ka[p];
            k2acc[p] += v.x * v.x + v.y * v.y + v.z * v.z + v.w * v.w;
            __nv_bfloat162 h0 = __floats2bfloat162_rn(v.x, v.y);
            __nv_bfloat162 h1 = __floats2bfloat162_rn(v.z, v.w);
            uint2 u;
            u.x = *(uint32_t*)&h0; u.y = *(uint32_t*)&h1;
            *(uint2*)&As2[s][row][lc4 * 4] = u;
        }
#pragma unroll
        for (int p = 0; p < 2; p++) {
            int row = lrow + 32 * p;
            float4 v = qa[p];
            __nv_bfloat162 h0 = __floats2bfloat162_rn(2.f * v.x, 2.f * v.y);
            __nv_bfloat162 h1 = __floats2bfloat162_rn(2.f * v.z, 2.f * v.w);
            uint2 u;
            u.x = *(uint32_t*)&h0; u.y = *(uint32_t*)&h1;
            *(uint2*)&Bs2[s][row][lc4 * 4] = u;
        }
    };
    auto compute = [&](int s) {
        uint32_t abase = (uint32_t)__cvta_generic_to_shared(&As2[s][0][0]);
        uint32_t bbase = (uint32_t)__cvta_generic_to_shared(&Bs2[s][0][0]);
        const int j = lid >> 3, r = lid & 7;
#pragma unroll
        for (int ks = 0; ks < 2; ks++) {
            uint32_t af[2][4], bfr[2][4];
#pragma unroll
            for (int mt = 0; mt < 2; mt++) {
                int arow = warp_m + mt * 16 + ((j & 1) << 3) + r;
                int acol = ks * 16 + ((j >> 1) << 3);
                ldsm_x4(af[mt], abase + (uint32_t)(arow * ASTRIDE + acol) * 2);
            }
#pragma unroll
            for (int pn = 0; pn < 2; pn++) {
                int brow = warp_n + pn * 16 + ((j >> 1) << 3) + r;
                int bcol = ks * 16 + ((j & 1) << 3);
                ldsm_x4(bfr[pn], bbase + (uint32_t)(brow * ASTRIDE + bcol) * 2);
            }
#pragma unroll
            for (int mt = 0; mt < 2; mt++)
#pragma unroll
                for (int nt = 0; nt < 4; nt++) {
                    uint32_t b2[2] = { bfr[nt >> 1][(nt & 1) * 2],
                                       bfr[nt >> 1][(nt & 1) * 2 + 1] };
                    mma_bf16(acc[mt][nt], af[mt], b2);
                }
        }
    };

    load_chunk(0);
    store_chunk(0);
    __syncthreads();

    for (int c = 0; c < NCH; c++) {
        const int s = c & 1;
        if (c + 1 < NCH) load_chunk(c + 1);
        compute(s);
        __syncthreads();
        if (c + 1 < NCH) {
            store_chunk(s ^ 1);
            __syncthreads();
        }
    }

    // reduce ||k||^2 (8 lanes per key row)
#pragma unroll
    for (int p = 0; p < 4; p++) {
        float v = k2acc[p];
        v += __shfl_xor_sync(0xFFFFFFFFu, v, 1);
        v += __shfl_xor_sync(0xFFFFFFFFu, v, 2);
        v += __shfl_xor_sync(0xFFFFFFFFu, v, 4);
        if ((tid & 7) == 0) k2sm[lrow + 32 * p] = v;
    }
    __syncthreads();

    // write scores (blocked layout)
    const size_t obase = (size_t)blockIdx.x * 64 * 128;
#pragma unroll
    for (int mt = 0; mt < 2; mt++) {
        int mb = warp_m + mt * 16 + (lid >> 2);
        float k2lo = k2sm[mb], k2hi = k2sm[mb + 8];
#pragma unroll
        for (int nt = 0; nt < 4; nt++) {
            int nn = warp_n + nt * 8 + (lid & 3) * 2;
            g_scores[obase + (size_t)nn * 128 + mb]           = acc[mt][nt][0] - k2lo;
            g_scores[obase + (size_t)(nn + 1) * 128 + mb]     = acc[mt][nt][1] - k2lo;
            g_scores[obase + (size_t)nn * 128 + mb + 8]       = acc[mt][nt][2] - k2hi;
            g_scores[obase + (size_t)(nn + 1) * 128 + mb + 8] = acc[mt][nt][3] - k2hi;
        }
    }
}

// ---------------------------------------------------------------------------
// Kernel B1: per-(row,chunk) top-8 over blocked scores. grid (TCH, BQ).
// ---------------------------------------------------------------------------
__global__ __launch_bounds__(256) void topk_stage1(void)
{
    const int ch  = blockIdx.x;
    const int row = blockIdx.y;
    const int tid = threadIdx.x;

    float tv[KNN]; int ti[KNN];
#pragma unroll
    for (int j = 0; j < KNN; j++) { tv[j] = -FLT_MAX; ti[j] = -1; }

    for (int i = tid; i < 128 * 32; i += 256) {
        const int kbl = i >> 5, j = i & 31;
        const int kb = ch * 128 + kbl;
        float4 s4 = *(const float4*)(g_scores + ((size_t)kb * 64 + row) * 128 + j * 4);
        float v[4] = {s4.x, s4.y, s4.z, s4.w};
#pragma unroll
        for (int l = 0; l < 4; l++) {
            if (v[l] > tv[0]) {
                tv[0] = v[l]; ti[0] = kb * 128 + j * 4 + l;
#pragma unroll
                for (int jj = 0; jj < KNN - 1; jj++) {
                    if (tv[jj] > tv[jj + 1]) {
                        float t0 = tv[jj]; tv[jj] = tv[jj+1]; tv[jj+1] = t0;
                        int   t1 = ti[jj]; ti[jj] = ti[jj+1]; ti[jj+1] = t1;
                    }
                }
            }
        }
    }

    __shared__ float sv[256 * KNN];
    __shared__ int   si[256 * KNN];
#pragma unroll
    for (int j = 0; j < KNN; j++) { sv[tid*KNN+j] = tv[j]; si[tid*KNN+j] = ti[j]; }

    __shared__ float rv[256];
    __shared__ int   rp[256];
    __syncthreads();

    for (int sel = 0; sel < KNN; sel++) {
        float bv = -FLT_MAX; int bp = 0;
#pragma unroll
        for (int j = 0; j < KNN; j++) {
            float v = sv[tid*KNN+j];
            if (v > bv) { bv = v; bp = tid*KNN+j; }
        }
        rv[tid] = bv; rp[tid] = bp;
        __syncthreads();
        for (int s = 128; s > 0; s >>= 1) {
            if (tid < s && rv[tid+s] > rv[tid]) { rv[tid] = rv[tid+s]; rp[tid] = rp[tid+s]; }
            __syncthreads();
        }
        if (tid == 0) {
            int p = rp[0];
            g_cand_v[(row * TCH + ch) * KNN + sel] = sv[p];
            g_cand_i[(row * TCH + ch) * KNN + sel] = si[p];
            sv[p] = -FLT_MAX;
        }
        __syncthreads();
    }
}

// ---------------------------------------------------------------------------
// Kernel B2: merge 128 bf16 candidates -> top-16, exact fp32 rescore,
// exact top-8 + weights + tokens.
// ---------------------------------------------------------------------------
__global__ __launch_bounds__(128) void topk_stage2(
    const float* __restrict__ Q, const float* __restrict__ Keys,
    const int* __restrict__ values)
{
    const int row = blockIdx.x;
    const int tid = threadIdx.x;
    const int wid = tid >> 5, lid = tid & 31;

    __shared__ float sv[128];
    __shared__ int   si[128];
    __shared__ float rv[128];
    __shared__ int   rp[128];
    __shared__ int   c16i[CAND16];
    __shared__ float c16s[CAND16];

    sv[tid] = g_cand_v[row * 128 + tid];
    si[tid] = g_cand_i[row * 128 + tid];
    __syncthreads();

    for (int sel = 0; sel < CAND16; sel++) {
        rv[tid] = sv[tid]; rp[tid] = tid;
        __syncthreads();
        for (int s = 64; s > 0; s >>= 1) {
            if (tid < s && rv[tid+s] > rv[tid]) { rv[tid] = rv[tid+s]; rp[tid] = rp[tid+s]; }
            __syncthreads();
        }
        if (tid == 0) {
            int p = rp[0];
            c16i[sel] = si[p];
            sv[p] = -FLT_MAX;
        }
        __syncthreads();
    }

    // exact fp32 rescore
    const float* qp = Q + (size_t)row * DIM;
    for (int c = wid; c < CAND16; c += 4) {
        const float* kp = Keys + (size_t)c16i[c] * DIM;
        float dot = 0.f, kk = 0.f;
        for (int j = lid; j < DIM; j += 32) {
            float kv = kp[j];
            dot = fmaf(qp[j], kv, dot);
            kk  = fmaf(kv, kv, kk);
        }
#pragma unroll
        for (int m = 16; m > 0; m >>= 1) {
            dot += __shfl_xor_sync(0xFFFFFFFFu, dot, m);
            kk  += __shfl_xor_sync(0xFFFFFFFFu, kk, m);
        }
        if (lid == 0) c16s[c] = 2.f * dot - kk;
    }
    __syncthreads();

    if (tid == 0) {
        float s16[CAND16]; int i16[CAND16];
#pragma unroll
        for (int j = 0; j < CAND16; j++) { s16[j] = c16s[j]; i16[j] = c16i[j]; }
        float topv[KNN]; int topi[KNN];
        for (int sel = 0; sel < KNN; sel++) {
            int best = -1;
            for (int j = 0; j < CAND16; j++) {
                if (i16[j] < 0) continue;
                if (best < 0 || s16[j] > s16[best] ||
                    (s16[j] == s16[best] && i16[j] < i16[best])) best = j;
            }
            topv[sel] = s16[best]; topi[sel] = i16[best];
            i16[best] = -1;
        }
        float m = topv[0];
        float e[KNN], sum = 0.f;
#pragma unroll
        for (int j = 0; j < KNN; j++) { e[j] = expf((topv[j] - m) * INV_TEMP); sum += e[j]; }
        float inv = 1.f / sum;
#pragma unroll
        for (int j = 0; j < KNN; j++) {
            g_w[row * KNN + j]   = e[j] * inv;
            g_tok[row * KNN + j] = values[topi[j]];
        }
    }
}

// ---------------------------------------------------------------------------
// Kernel E1/E2: softmax partials + mix.
// ---------------------------------------------------------------------------
#define VCH ((VOCAB + ECH - 1) / ECH)

__global__ __launch_bounds__(256) void epi_partials(const float* __restrict__ base)
{
    const int chunk = blockIdx.x;
    const int row   = blockIdx.y;
    const int tid   = threadIdx.x;
    const int start = chunk * VCH;
    const int end   = min(start + VCH, VOCAB);
    const float* br = base + (size_t)row * VOCAB;

    __shared__ float red[256];

    float m = -FLT_MAX;
    for (int i = start + tid; i < end; i += 256) m = fmaxf(m, br[i]);
    red[tid] = m; __syncthreads();
    for (int s = 128; s > 0; s >>= 1) {
        if (tid < s) red[tid] = fmaxf(red[tid], red[tid+s]);
        __syncthreads();
    }
    const float mx = red[0];
    __syncthreads();

    float sacc = 0.f;
    for (int i = start + tid; i < end; i += 256) sacc += expf(br[i] - mx);
    red[tid] = sacc; __syncthreads();
    for (int s = 128; s > 0; s >>= 1) {
        if (tid < s) red[tid] += red[tid+s];
        __syncthreads();
    }
    if (tid == 0) g_ms[row * ECH + chunk] = make_float2(mx, red[0]);
}

__global__ __launch_bounds__(256) void epi_write(
    const float* __restrict__ base, float* __restrict__ out)
{
    const int chunk = blockIdx.x;
    const int row   = blockIdx.y;
    const int tid   = threadIdx.x;
    const int start = chunk * VCH;
    const int end   = min(start + VCH, VOCAB);
    const float* br = base + (size_t)row * VOCAB;

    float mx = -FLT_MAX;
#pragma unroll
    for (int c = 0; c < ECH; c++) mx = fmaxf(mx, g_ms[row * ECH + c].x);
    float Z = 0.f;
#pragma unroll
    for (int c = 0; c < ECH; c++) {
        float2 p = g_ms[row * ECH + c];
        Z += p.y * expf(p.x - mx);
    }
    const float invZ = 1.f / Z;

    float w[KNN]; int tk[KNN];
#pragma unroll
    for (int j = 0; j < KNN; j++) { w[j] = g_w[row*KNN+j]; tk[j] = g_tok[row*KNN+j]; }

    const float invden = 1.f / (1.f + (float)VOCAB * EPSV);

    float* oi = out + (size_t)row * VOCAB;
    float* ob = out + (size_t)BQ * VOCAB + (size_t)row * VOCAB;
    float* ok = out + (size_t)2 * BQ * VOCAB + (size_t)row * VOCAB;

    for (int i = start + tid; i < end; i += 256) {
        float b  = br[i];
        float sb = expf(b - mx) * invZ;
        float tp = 0.f;
#pragma unroll
        for (int j = 0; j < KNN; j++) tp += (tk[j] == i) ? w[j] : 0.f;
        float p = (1.f - LAM) * sb + LAM * (tp + EPSV) * invden;
        oi[i] = logf(p);
        ob[i] = b;
        ok[i] = logf(tp + EPSV);
    }
}

// ---------------------------------------------------------------------------
extern "C" void kernel_launch(void* const* d_in, const int* in_sizes, int n_in,
                              void* d_out, int out_size)
{
    const float* Q    = (const float*)d_in[0];
    const float* BL   = (const float*)d_in[1];
    const float* Keys = (const float*)d_in[2];
    const int*   Vals = (const int*)d_in[3];
    float* out = (float*)d_out;

    gemm_mma_kernel<<<NKB, 256>>>(Q, Keys);
    topk_stage1<<<dim3(TCH, BQ), 256>>>();
    topk_stage2<<<BQ, 128>>>(Q, Keys, Vals);
    epi_partials<<<dim3(ECH, BQ), 256>>>(BL);
    epi_write<<<dim3(ECH, BQ), 256>>>(BL, out);
}